// round 16
// baseline (speedup 1.0000x reference)
#include <cuda_runtime.h>
#include <cuda_fp16.h>
#include <cstdint>
#include <math.h>
#include <mma.h>
using namespace nvcuda;

// ---------------- model constants ----------------
#define BATCH   512
#define S_LEN   215
#define DINP    36
#define DMODEL  144
#define DT      160
#define NHEAD   4
#define DH      40
#define NHID    128
#define FIN     860
#define FINP    896
#define DTP     192
#define DFINAL  196
#define NROWS_GAT (BATCH*DINP)          // 18432
#define NROWS_TR  (S_LEN*BATCH)         // 110080

// ---------------- scratch (device globals; zero-initialized at load) ----------------
__device__ float  g_bufA[(size_t)NROWS_GAT*FIN];    // H2 fp32 (feeds build_out)
__device__ float  g_ps[NROWS_GAT];
__device__ float  g_pd[NROWS_GAT];
__device__ float  g_alpha1[(size_t)BATCH*DINP*DINP];
__device__ float  g_alpha2[(size_t)BATCH*DINP*DINP];
__device__ float  g_sq[BATCH];
__device__ float  g_part[BATCH];
__device__ float  g_x[(size_t)NROWS_TR*DT];         // fp32 residual highway
__device__ float  g_feat[BATCH*DFINAL];
// fp16 operands; pad columns never written -> stay zero (module zero-init)
__device__ __half g_hgat[(size_t)NROWS_GAT*FINP];
__device__ __half g_hXP[(size_t)NROWS_GAT*FIN];
__device__ __half g_hx[(size_t)NROWS_TR*DTP];
__device__ __half g_hatt[(size_t)NROWS_TR*DTP];
__device__ __half g_hff[(size_t)NROWS_TR*NHID];
__device__ __half g_qkvh[(size_t)NROWS_TR*3*DT];
#define WALL_TOTAL 2015232
__device__ __half g_hWall[WALL_TOTAL];

// ---------------- utility ----------------
__global__ void zero_kernel(float* p, int n) {
    int i = blockIdx.x*blockDim.x + threadIdx.x;
    if (i < n) p[i] = 0.f;
}

__device__ __forceinline__ void cp16(uint32_t dst, const void* src) {
    asm volatile("cp.async.cg.shared.global [%0], [%1], 16;\n" :: "r"(dst), "l"(src));
}
__device__ __forceinline__ void cp_commit() {
    asm volatile("cp.async.commit_group;\n" ::: "memory");
}
__device__ __forceinline__ void cp_wait_all() {
    asm volatile("cp.async.wait_group 0;\n" ::: "memory");
}

// ---------------- all-weights transpose+convert (one launch) ----------------
struct WSeg { const float* src; int K, N, Kp, Npad; long off; };
struct WSegs { WSeg s[10]; };

__global__ void convW_kernel(WSegs segs, long total)
{
    long g = (long)blockIdx.x*blockDim.x + threadIdx.x;
    if (g >= total) return;
    int si = 0;
    #pragma unroll
    for (int i = 1; i < 10; i++) if (g >= segs.s[i].off) si = i;
    const WSeg& sg = segs.s[si];
    long i = g - sg.off;
    int k = (int)(i % sg.Kp), n = (int)(i / sg.Kp);
    float v = (k < sg.K && n < sg.N) ? sg.src[(size_t)k*sg.N + n] : 0.f;
    g_hWall[g] = __float2half(v);
}

// ---------------- FP16 tensor-core GEMM (256 thr, warp tile 64x32) ----------------
#define HKT 64
#define HLD 72
#define HSTG (128*HLD)
#define HSMEM (4*HSTG*2)
#define WLD 20

__global__ void __launch_bounds__(256, 2)
hgemm16_kernel(const __half* __restrict__ Ah, const __half* __restrict__ Bt,
               float* __restrict__ Cf, __half* __restrict__ Ch,
               int M, int N, int Kp, int ldc,
               const float* __restrict__ bias, int relu_flag)
{
    extern __shared__ __half hs[];
    __half* As0 = hs;
    __half* Bs0 = hs + HSTG;
    __half* As1 = hs + 2*HSTG;
    __half* Bs1 = hs + 3*HSTG;
    __shared__ float Wb[8][16*WLD];

    int tid = threadIdx.x;
    int warpId = tid >> 5, lane = tid & 31;
    int wr = warpId >> 2;
    int wc = warpId & 3;
    int row0 = blockIdx.y*128, col0 = blockIdx.x*128;

    wmma::fragment<wmma::accumulator,16,16,16,float> cf[4][2];
    #pragma unroll
    for (int i=0;i<4;i++)
      #pragma unroll
      for (int j=0;j<2;j++) wmma::fill_fragment(cf[i][j], 0.f);

    const int nIter = Kp / HKT;

    auto load_stage = [&](__half* as, __half* bs, int k0) {
        #pragma unroll
        for (int c = 0; c < 4; c++) {
            int ci = tid + c*256;
            int r = ci >> 3, c8 = (ci & 7)*8;
            cp16((uint32_t)__cvta_generic_to_shared(&as[r*HLD + c8]),
                 &Ah[(size_t)(row0 + r)*Kp + k0 + c8]);
        }
        #pragma unroll
        for (int c = 0; c < 4; c++) {
            int ci = tid + c*256;
            int r = ci >> 3, c8 = (ci & 7)*8;
            cp16((uint32_t)__cvta_generic_to_shared(&bs[r*HLD + c8]),
                 &Bt[(size_t)(col0 + r)*Kp + k0 + c8]);
        }
        cp_commit();
    };

    load_stage(As0, Bs0, 0);

    for (int it = 0; it < nIter; it++) {
        cp_wait_all();
        __syncthreads();
        __half* as = (it & 1) ? As1 : As0;
        __half* bs = (it & 1) ? Bs1 : Bs0;
        if (it + 1 < nIter)
            load_stage((it & 1) ? As0 : As1, (it & 1) ? Bs0 : Bs1, (it+1)*HKT);

        #pragma unroll
        for (int ks = 0; ks < HKT; ks += 16) {
            wmma::fragment<wmma::matrix_a,16,16,16,__half,wmma::row_major> af[4];
            wmma::fragment<wmma::matrix_b,16,16,16,__half,wmma::col_major> bf[2];
            #pragma unroll
            for (int fr=0; fr<4; fr++)
                wmma::load_matrix_sync(af[fr], &as[(wr*64 + fr*16)*HLD + ks], HLD);
            #pragma unroll
            for (int fc=0; fc<2; fc++)
                wmma::load_matrix_sync(bf[fc], &bs[(wc*32 + fc*16)*HLD + ks], HLD);
            #pragma unroll
            for (int fr=0; fr<4; fr++)
              #pragma unroll
              for (int fc=0; fc<2; fc++)
                wmma::mma_sync(cf[fr][fc], af[fr], bf[fc], cf[fr][fc]);
        }
        __syncthreads();
    }

    float* wbuf = Wb[warpId];
    #pragma unroll
    for (int fr=0; fr<4; fr++) {
        #pragma unroll
        for (int fc=0; fc<2; fc++) {
            wmma::store_matrix_sync(wbuf, cf[fr][fc], WLD, wmma::mem_row_major);
            __syncwarp();
            int rb = row0 + wr*64 + fr*16;
            int cb = col0 + wc*32 + fc*16;
            #pragma unroll
            for (int i = lane; i < 256; i += 32) {
                int r = i >> 4, c = i & 15;
                int gc = cb + c;
                if (gc < N) {
                    float v = wbuf[r*WLD + c];
                    if (bias) v += bias[gc];
                    if (relu_flag) v = fmaxf(v, 0.f);
                    size_t off = (size_t)(rb + r)*ldc + gc;
                    if (Cf) Cf[off] = v;
                    if (Ch) Ch[off] = __float2half(v);
                }
            }
            __syncwarp();
        }
    }
}

// ---------------- fused GEMM + residual + LayerNorm (N=160, 320 thr, 2x5 warps) ----------------
// out_row = LN(A@Bt^T + bias + x_row); writes fp32 x (ld DT) and fp16 hx (ld DTP).
#define F_ASTG (128*HLD)     // 9216 halves
#define F_BSTG (160*HLD)     // 11520 halves
#define FSMEM_STAGE ((F_ASTG+F_BSTG)*2*2)   // 82944 B
#define FSMEM_EPI   (128*160*4)             // 81920 B
#define FSMEM (FSMEM_STAGE > FSMEM_EPI ? FSMEM_STAGE : FSMEM_EPI)

__global__ void __launch_bounds__(320)
hgemm_ln_kernel(const __half* __restrict__ Ah, const __half* __restrict__ Bt,
                float* __restrict__ xio, __half* __restrict__ hxo,
                int Kp, const float* __restrict__ bias,
                const float* __restrict__ lg, const float* __restrict__ lb)
{
    extern __shared__ __half hs[];
    __half* As0 = hs;
    __half* Bs0 = hs + F_ASTG;
    __half* As1 = Bs0 + F_BSTG;
    __half* Bs1 = As1 + F_ASTG;
    float* Cs = (float*)hs;     // reused after mainloop

    int tid = threadIdx.x;
    int w = tid >> 5, lane = tid & 31;
    int wr = w / 5, wc = w - wr*5;     // 2 x 5 warps, warp tile 64x32
    int row0 = blockIdx.x * 128;

    wmma::fragment<wmma::accumulator,16,16,16,float> cf[4][2];
    #pragma unroll
    for (int i=0;i<4;i++)
      #pragma unroll
      for (int j=0;j<2;j++) wmma::fill_fragment(cf[i][j], 0.f);

    const int nIter = Kp / HKT;

    auto load_stage = [&](__half* as, __half* bs, int k0) {
        #pragma unroll
        for (int c = 0; c < 4; c++) {            // A: 1024 chunks
            int ci = tid + c*320;
            if (ci < 1024) {
                int r = ci >> 3, c8 = (ci & 7)*8;
                cp16((uint32_t)__cvta_generic_to_shared(&as[r*HLD + c8]),
                     &Ah[(size_t)(row0 + r)*Kp + k0 + c8]);
            }
        }
        #pragma unroll
        for (int c = 0; c < 4; c++) {            // B: 1280 chunks, exact
            int ci = tid + c*320;
            int r = ci >> 3, c8 = (ci & 7)*8;
            cp16((uint32_t)__cvta_generic_to_shared(&bs[r*HLD + c8]),
                 &Bt[(size_t)r*Kp + k0 + c8]);
        }
        cp_commit();
    };

    load_stage(As0, Bs0, 0);

    for (int it = 0; it < nIter; it++) {
        cp_wait_all();
        __syncthreads();
        __half* as = (it & 1) ? As1 : As0;
        __half* bs = (it & 1) ? Bs1 : Bs0;
        if (it + 1 < nIter)
            load_stage((it & 1) ? As0 : As1, (it & 1) ? Bs0 : Bs1, (it+1)*HKT);

        #pragma unroll
        for (int ks = 0; ks < HKT; ks += 16) {
            wmma::fragment<wmma::matrix_a,16,16,16,__half,wmma::row_major> af[4];
            wmma::fragment<wmma::matrix_b,16,16,16,__half,wmma::col_major> bf[2];
            #pragma unroll
            for (int fr=0; fr<4; fr++)
                wmma::load_matrix_sync(af[fr], &as[(wr*64 + fr*16)*HLD + ks], HLD);
            #pragma unroll
            for (int fc=0; fc<2; fc++)
                wmma::load_matrix_sync(bf[fc], &bs[(wc*32 + fc*16)*HLD + ks], HLD);
            #pragma unroll
            for (int fr=0; fr<4; fr++)
              #pragma unroll
              for (int fc=0; fc<2; fc++)
                wmma::mma_sync(cf[fr][fc], af[fr], bf[fc], cf[fr][fc]);
        }
        __syncthreads();
    }

    // epilogue: stage full 128x160 fp32 tile, then warp-per-row residual+LN
    #pragma unroll
    for (int fr=0; fr<4; fr++)
      #pragma unroll
      for (int fc=0; fc<2; fc++)
        wmma::store_matrix_sync(&Cs[(wr*64 + fr*16)*160 + wc*32 + fc*16],
                                cf[fr][fc], 160, wmma::mem_row_major);
    __syncthreads();

    for (int r = w; r < 128; r += 10) {
        size_t grow = (size_t)(row0 + r);
        float v[5];
        float s = 0.f, q = 0.f;
        #pragma unroll
        for (int i=0;i<5;i++){
            int c = lane + 32*i;
            float val = Cs[r*160 + c] + bias[c] + xio[grow*DT + c];
            v[i]=val; s += val; q += val*val;
        }
        #pragma unroll
        for (int o=16;o>0;o>>=1){
            s += __shfl_xor_sync(0xffffffffu, s, o);
            q += __shfl_xor_sync(0xffffffffu, q, o);
        }
        float mean = s/(float)DT;
        float var  = q/(float)DT - mean*mean;
        float inv  = rsqrtf(var + 1e-5f);
        #pragma unroll
        for (int i=0;i<5;i++){
            int d = lane + 32*i;
            float rr = (v[i]-mean)*inv*lg[d] + lb[d];
            xio[grow*DT + d] = rr;
            hxo[grow*DTP + d] = __float2half(rr);
        }
    }
}

// ---------------- GAT ----------------
__global__ void build_x_kernel(const float* __restrict__ src, const float* __restrict__ R_u)
{
    size_t n = (size_t)blockIdx.x*blockDim.x + threadIdx.x;
    const size_t total = (size_t)NROWS_GAT*FIN;
    if (n >= total) return;
    int c = (int)(n % FIN);
    int row = (int)(n / FIN);
    int i = row % DINP, b = row / DINP;
    int s = c >> 2, o = c & 3;
    float v = src[((size_t)s*BATCH + b)*(2*DINP) + i];
    g_hgat[(size_t)row*FINP + c] = __float2half(fmaxf(v * R_u[i*4+o], 0.f));
}

#define FIN2 (FIN/2)   // 430
__global__ void psd_kernel(const __half* __restrict__ XP,
                           const float* __restrict__ a_s, const float* __restrict__ a_d)
{
    int row = blockIdx.x;
    const __half2* x2 = (const __half2*)(XP + (size_t)row*FIN);
    int t = threadIdx.x;
    float s1=0.f, s2=0.f;
    for (int c2=t; c2<FIN2; c2+=256) {
        float2 v = __half22float2(x2[c2]);
        s1 += v.x*a_s[2*c2] + v.y*a_s[2*c2+1];
        s2 += v.x*a_d[2*c2] + v.y*a_d[2*c2+1];
    }
    __shared__ float r1[256], r2[256];
    r1[t]=s1; r2[t]=s2; __syncthreads();
    for (int o=128;o>0;o>>=1){ if(t<o){r1[t]+=r1[t+o]; r2[t]+=r2[t+o];} __syncthreads(); }
    if (t==0){ g_ps[row]=r1[0]; g_pd[row]=r2[0]; }
}

__global__ void alpha_kernel(const float* __restrict__ edge, float* __restrict__ alpha)
{
    int b = blockIdx.x;
    int i = threadIdx.x;
    if (i >= DINP) return;
    const float* psb = g_ps + b*DINP;
    float pdi = g_pd[b*DINP+i];
    float e[DINP];
    float m = -1e30f;
    #pragma unroll
    for (int j=0;j<DINP;j++){
        float v = pdi + psb[j];
        v = (v > 0.f) ? v : 0.2f*v;
        e[j]=v; m = fmaxf(m,v);
    }
    float l=0.f;
    #pragma unroll
    for (int j=0;j<DINP;j++){ float w=expf(e[j]-m); e[j]=w; l+=w; }
    float inv = 1.f/l;
    size_t base = ((size_t)b*DINP + i)*DINP;
    #pragma unroll
    for (int j=0;j<DINP;j++){
        float a = e[j]*inv;
        if (edge) a *= edge[base+j];
        alpha[base+j] = a;
    }
}

// H = alpha @ XP ; fp16 (ld FINP) and/or fp32 (ld FIN)
__global__ void gat_agg_kernel(const float* __restrict__ alpha, const __half* __restrict__ XP,
                               __half* __restrict__ Hh, float* __restrict__ Hf)
{
    int b = blockIdx.x;
    __shared__ float al[DINP*DINP];
    for (int i=threadIdx.x;i<DINP*DINP;i+=blockDim.x) al[i]=alpha[(size_t)b*DINP*DINP+i];
    __syncthreads();
    const __half2* xp = (const __half2*)(XP + (size_t)b*DINP*FIN);
    for (int idx=threadIdx.x; idx<DINP*FIN2; idx+=blockDim.x){
        int i = idx/FIN2, c2 = idx%FIN2;
        float s0=0.f, s1=0.f;
        #pragma unroll 6
        for (int j=0;j<DINP;j++){
            float a = al[i*DINP+j];
            float2 v = __half22float2(xp[j*FIN2 + c2]);
            s0 += a*v.x; s1 += a*v.y;
        }
        size_t row = (size_t)b*DINP + i;
        if (Hh) *(__half2*)&Hh[row*FINP + 2*c2] = __floats2half2_rn(s0, s1);
        if (Hf) { Hf[row*FIN + 2*c2] = s0; Hf[row*FIN + 2*c2+1] = s1; }
    }
}

__global__ void sq_kernel(const float* __restrict__ A)
{
    int b = blockIdx.x; int t = threadIdx.x;
    float s=0.f;
    for (int i=t;i<DINP*DINP;i+=256){ float v=A[(size_t)b*DINP*DINP+i]; s+=v*v; }
    __shared__ float r[256];
    r[t]=s; __syncthreads();
    for (int o=128;o>0;o>>=1){ if(t<o) r[t]+=r[t+o]; __syncthreads(); }
    if (t==0) g_sq[b]=r[0];
}

// ---------------- tiled pairwise distance ----------------
#define DTILE 64
#define DCH 64
#define KD (DINP*DINP)   // 1296
__global__ void dist_kernel(const float* __restrict__ A, float* __restrict__ partial)
{
    __shared__ float As[DTILE][DCH+5];
    __shared__ float Bs[DTILE][DCH+5];
    int i0 = blockIdx.y*DTILE, j0 = blockIdx.x*DTILE;
    int t = threadIdx.x;
    int tx = t & 15, ty = t >> 4;
    float dot[4][4];
    #pragma unroll
    for (int a=0;a<4;a++)
      #pragma unroll
      for (int b=0;b<4;b++) dot[a][b]=0.f;

    for (int c0 = 0; c0 < KD; c0 += DCH) {
        for (int l = t; l < DTILE*DCH; l += 256) {
            int r = l >> 6, c = l & 63;
            int gc = c0 + c;
            float va = 0.f, vb = 0.f;
            if (gc < KD) {
                va = A[(size_t)(i0+r)*KD + gc];
                vb = A[(size_t)(j0+r)*KD + gc];
            }
            As[r][c] = va;
            Bs[r][c] = vb;
        }
        __syncthreads();
        #pragma unroll 8
        for (int c = 0; c < DCH; c++) {
            float a[4], b[4];
            #pragma unroll
            for (int ii=0;ii<4;ii++) a[ii] = As[ty*4+ii][c];
            #pragma unroll
            for (int jj=0;jj<4;jj++) b[jj] = Bs[tx*4+jj][c];
            #pragma unroll
            for (int ii=0;ii<4;ii++)
              #pragma unroll
              for (int jj=0;jj<4;jj++) dot[ii][jj] += a[ii]*b[jj];
        }
        __syncthreads();
    }

    float loc = 0.f;
    #pragma unroll
    for (int ii=0;ii<4;ii++) {
        int i = i0 + ty*4 + ii;
        float sqi = g_sq[i];
        #pragma unroll
        for (int jj=0;jj<4;jj++) {
            int j = j0 + tx*4 + jj;
            float d2 = sqi + g_sq[j] - 2.f*dot[ii][jj];
            d2 = fmaxf(d2, 0.f);
            loc += sqrtf(d2 + 1e-12f);
        }
    }
    __shared__ float red[256];
    red[t] = loc; __syncthreads();
    for (int o=128;o>0;o>>=1){ if(t<o) red[t]+=red[t+o]; __syncthreads(); }
    if (t==0) partial[blockIdx.y*8 + blockIdx.x] = red[0];
}

__global__ void fin_dist_kernel(float* __restrict__ out, int out_size)
{
    if (threadIdx.x==0){
        float s=0.f;
        for (int i=0;i<64;i++) s += g_part[i];
        if (out_size > BATCH*2) out[BATCH*2] = s / ((float)BATCH*(float)BATCH);
    }
}

// ---------------- transformer input: fp32 x + fp16 mirror ----------------
__global__ void build_out_kernel(const float* __restrict__ times)
{
    size_t n = (size_t)blockIdx.x*blockDim.x + threadIdx.x;
    const size_t total = (size_t)NROWS_TR*DT;
    if (n >= total) return;
    int d = (int)(n % DT);
    size_t row = n / DT;
    int b = (int)(row % BATCH);
    int s = (int)(row / BATCH);
    float v;
    if (d < DMODEL) {
        v = g_bufA[((size_t)b*DINP + (d>>2))*FIN + s*4 + (d&3)];
    } else {
        int k = d - DMODEL;
        float tv = times[(size_t)s*BATCH + b];
        int kk = (k < 8) ? k : k-8;
        float ts = powf(215.0f, (float)kk/7.0f) * 100.0f;
        float sc = tv / ts;
        v = (k < 8) ? sinf(sc) : cosf(sc);
    }
    g_x[n] = v;
    g_hx[row*DTP + d] = __float2half(v);
}

// ---------------- tensor-core flash-style attention ----------------
#define AQ_ROWS 224
#define ALD 48
#define ATTN_SMEM (3*AQ_ROWS*ALD*2 + 8*256*4 + 8*256*2 + 8*16*48*4)
#define PSCALE 0.015625f

__global__ void __launch_bounds__(256)
attn_kernel(const __half* __restrict__ qkv, const int* __restrict__ lengths,
            __half* __restrict__ outh)
{
    extern __shared__ char smc[];
    __half* Qs = (__half*)smc;
    __half* Ks = Qs + AQ_ROWS*ALD;
    __half* Vs = Ks + AQ_ROWS*ALD;
    float*  Ss = (float*)(smc + 3*AQ_ROWS*ALD*2);
    __half* Ps = (__half*)(smc + 3*AQ_ROWS*ALD*2 + 8*256*4);
    float*  Os = (float*)(smc + 3*AQ_ROWS*ALD*2 + 8*256*4 + 8*256*2);

    int b = blockIdx.x, h = blockIdx.y;
    int tid = threadIdx.x;
    int w = tid >> 5, lane = tid & 31;
    int len = lengths[b];

    {
        uint32_t* z = (uint32_t*)smc;
        for (int i = tid; i < 3*AQ_ROWS*ALD/2; i += 256) z[i] = 0u;
    }
    __syncthreads();
    for (int idx = tid; idx < S_LEN*20; idx += 256) {
        int t = idx / 20, d2 = idx % 20;
        size_t base = ((size_t)t*BATCH + b)*(3*DT) + h*DH + 2*d2;
        __half2 qv = *(const __half2*)&qkv[base];
        __half2 kv = *(const __half2*)&qkv[base + DT];
        __half2 vv = *(const __half2*)&qkv[base + 2*DT];
        *(__half2*)&Qs[t*ALD + 2*d2] = qv;
        *(__half2*)&Ks[t*ALD + 2*d2] = kv;
        *(__half2*)&Vs[t*ALD + 2*d2] = vv;
    }
    for (int t = tid; t < AQ_ROWS; t += 256) Vs[t*ALD + 40] = __float2half(1.f);
    __syncthreads();

    const float scale = rsqrtf((float)DH);
    float* mySs = Ss + w*256;
    __half* myPs = Ps + w*256;
    float* myOs = Os + w*768;
    int nkt = (len + 15) >> 4;

    #pragma unroll
    for (int qi = 0; qi < 2; qi++) {
        int qt = w + qi*8;
        if (qt >= 14) continue;
        int rowbase = qt*16;

        wmma::fragment<wmma::accumulator,16,16,16,float> acc[3];
        #pragma unroll
        for (int n=0;n<3;n++) wmma::fill_fragment(acc[n], 0.f);

        for (int kt = 0; kt < nkt; kt++) {
            int kbase = kt*16;
            wmma::fragment<wmma::accumulator,16,16,16,float> sf;
            wmma::fill_fragment(sf, 0.f);
            #pragma unroll
            for (int kk = 0; kk < 3; kk++) {
                wmma::fragment<wmma::matrix_a,16,16,16,__half,wmma::row_major> qa;
                wmma::fragment<wmma::matrix_b,16,16,16,__half,wmma::col_major> kb;
                wmma::load_matrix_sync(qa, &Qs[rowbase*ALD + kk*16], ALD);
                wmma::load_matrix_sync(kb, &Ks[kbase*ALD + kk*16], ALD);
                wmma::mma_sync(sf, qa, kb, sf);
            }
            wmma::store_matrix_sync(mySs, sf, 16, wmma::mem_row_major);
            __syncwarp();
            #pragma unroll
            for (int e = lane; e < 256; e += 32) {
                int c = e & 15;
                int t = kbase + c;
                float wv = (t < len) ? __expf(mySs[e]*scale)*PSCALE : 0.f;
                myPs[e] = __float2half(wv);
            }
            __syncwarp();
            wmma::fragment<wmma::matrix_a,16,16,16,__half,wmma::row_major> pa;
            wmma::load_matrix_sync(pa, myPs, 16);
            #pragma unroll
            for (int n = 0; n < 3; n++) {
                wmma::fragment<wmma::matrix_b,16,16,16,__half,wmma::row_major> vb;
                wmma::load_matrix_sync(vb, &Vs[kbase*ALD + n*16], ALD);
                wmma::mma_sync(acc[n], pa, vb, acc[n]);
            }
        }

        #pragma unroll
        for (int n = 0; n < 3; n++)
            wmma::store_matrix_sync(&myOs[n*16], acc[n], ALD, wmma::mem_row_major);
        __syncwarp();

        #pragma unroll
        for (int e = lane; e < 16*20; e += 32) {
            int r = e / 20, d2 = e % 20;
            int s = rowbase + r;
            if (s >= S_LEN) continue;
            float inv = 1.f / myOs[r*ALD + 40];
            float o0 = myOs[r*ALD + 2*d2] * inv;
            float o1 = myOs[r*ALD + 2*d2+1] * inv;
            size_t ob = ((size_t)s*BATCH + b)*DTP + h*DH + 2*d2;
            *(__half2*)&outh[ob] = __floats2half2_rn(o0, o1);
        }
        __syncwarp();
    }
}

// ---------------- pooled features + static embedding ----------------
__global__ void agg_emb_kernel(const int* __restrict__ lengths,
                               const float* __restrict__ statics,
                               const float* __restrict__ emb_w, const float* __restrict__ emb_b)
{
    int b = blockIdx.x; int d = threadIdx.x;
    int len = lengths[b];
    if (d < DT) {
        float s = 0.f;
        for (int t=0;t<len;t++) s += g_x[((size_t)t*BATCH + b)*DT + d];
        g_feat[b*DFINAL+d] = s / ((float)len + 1.0f);
    } else if (d < DFINAL) {
        int j = d - DT;
        float s = emb_b[j];
        #pragma unroll
        for (int r=0;r<9;r++) s += statics[b*9+r]*emb_w[r*DINP+j];
        g_feat[b*DFINAL+d] = s;
    }
}

// ---------------- final MLP ----------------
__global__ void mlp_kernel(const float* __restrict__ w1, const float* __restrict__ b1,
                           const float* __restrict__ w2, const float* __restrict__ b2,
                           float* __restrict__ out)
{
    int b = blockIdx.x; int t = threadIdx.x;
    __shared__ float f[DFINAL], hd[DFINAL];
    f[t] = g_feat[b*DFINAL+t];
    __syncthreads();
    float s = b1[t];
    for (int r=0;r<DFINAL;r++) s += f[r]*w1[r*DFINAL+t];
    hd[t] = fmaxf(s, 0.f);
    __syncthreads();
    if (t < 2) {
        float s2 = b2[t];
        for (int r=0;r<DFINAL;r++) s2 += hd[r]*w2[r*2+t];
        out[b*2+t] = s2;
    }
}

// ---------------- launch ----------------
extern "C" void kernel_launch(void* const* d_in, const int* in_sizes, int n_in,
                              void* d_out, int out_size)
{
    const float* src    = (const float*)d_in[0];
    const float* statics= (const float*)d_in[1];
    const float* times  = (const float*)d_in[2];
    const int*   lengths= (const int*)d_in[3];
    const float* R_u    = (const float*)d_in[4];
    const float* emb_w  = (const float*)d_in[5];
    const float* emb_b  = (const float*)d_in[6];
    const float* W1     = (const float*)d_in[7];
    const float* a1_s   = (const float*)d_in[8];
    const float* a1_d   = (const float*)d_in[9];
    const float* W2     = (const float*)d_in[10];
    const float* a2_s   = (const float*)d_in[11];
    const float* a2_d   = (const float*)d_in[12];
    const float* attn_in_w  = (const float*)d_in[13];
    const float* attn_in_b  = (const float*)d_in[14];
    const float* attn_out_w = (const float*)d_in[15];
    const float* attn_out_b = (const float*)d_in[16];
    const float* ff1_w  = (const float*)d_in[17];
    const float* ff1_b  = (const float*)d_in[18];
    const float* ff2_w  = (const float*)d_in[19];
    const float* ff2_b  = (const float*)d_in[20];
    const float* ln1_g  = (const float*)d_in[21];
    const float* ln1_b  = (const float*)d_in[22];
    const float* ln2_g  = (const float*)d_in[23];
    const float* ln2_b  = (const float*)d_in[24];
    const float* mlp1_w = (const float*)d_in[25];
    const float* mlp1_b = (const float*)d_in[26];
    const float* mlp2_w = (const float*)d_in[27];
    const float* mlp2_b = (const float*)d_in[28];
    float* out = (float*)d_out;

    float *bufA, *al1, *al2, *x, *part;
    __half *hgat, *hXP, *hx, *hatt, *hff, *qkvh, *hWall;
    cudaGetSymbolAddress((void**)&bufA, g_bufA);
    cudaGetSymbolAddress((void**)&al1,  g_alpha1);
    cudaGetSymbolAddress((void**)&al2,  g_alpha2);
    cudaGetSymbolAddress((void**)&x,    g_x);
    cudaGetSymbolAddress((void**)&part, g_part);
    cudaGetSymbolAddress((void**)&hgat, g_hgat);
    cudaGetSymbolAddress((void**)&hXP,  g_hXP);
    cudaGetSymbolAddress((void**)&hx,   g_hx);
    cudaGetSymbolAddress((void**)&hatt, g_hatt);
    cudaGetSymbolAddress((void**)&hff,  g_hff);
    cudaGetSymbolAddress((void**)&qkvh, g_qkvh);
    cudaGetSymbolAddress((void**)&hWall,g_hWall);

    static bool attr_done = false;
    if (!attr_done) {
        cudaFuncSetAttribute(attn_kernel,
                             cudaFuncAttributeMaxDynamicSharedMemorySize, ATTN_SMEM);
        cudaFuncSetAttribute(hgemm16_kernel,
                             cudaFuncAttributeMaxDynamicSharedMemorySize, HSMEM);
        cudaFuncSetAttribute(hgemm_ln_kernel,
                             cudaFuncAttributeMaxDynamicSharedMemorySize, FSMEM);
        attr_done = true;
    }

    const long WOFF[10] = {0, 802816, 1605632, 1703936, 1802240, 1851392,
                           1900544, 1925120, 1949696, 1982464};
    WSegs segs;
    segs.s[0] = { W1, 860, 860, 896, 896, WOFF[0] };
    segs.s[1] = { W2, 860, 860, 896, 896, WOFF[1] };
    segs.s[2] = { attn_in_w,               160, 480, 192, 512, WOFF[2] };
    segs.s[3] = { attn_in_w + 160*480,     160, 480, 192, 512, WOFF[3] };
    segs.s[4] = { attn_out_w,              160, 160, 192, 256, WOFF[4] };
    segs.s[5] = { attn_out_w + 160*160,    160, 160, 192, 256, WOFF[5] };
    segs.s[6] = { ff1_w,                   160, 128, 192, 128, WOFF[6] };
    segs.s[7] = { ff1_w + 160*128,         160, 128, 192, 128, WOFF[7] };
    segs.s[8] = { ff2_w,                   128, 160, 128, 256, WOFF[8] };
    segs.s[9] = { ff2_w + 128*160,         128, 160, 128, 256, WOFF[9] };

    auto gemm = [&](const __half* Ah, int widx, int Kp, int Npad,
                    float* Cf, __half* Ch, int M, int N, int ldc,
                    const float* bias, int relu) {
        dim3 g(Npad/128, M/128);
        hgemm16_kernel<<<g,256,HSMEM>>>(Ah, hWall + WOFF[widx], Cf, Ch,
                                        M, N, Kp, ldc, bias, relu);
    };

    // launch order: zero(1) build_x(2) convW(3) hgemm(4) <- ncu window
    zero_kernel<<<(out_size+255)/256, 256>>>(out, out_size);

    {
        size_t nx = (size_t)NROWS_GAT*FIN;
        build_x_kernel<<<(unsigned)((nx+255)/256), 256>>>(src, R_u);
        convW_kernel<<<(WALL_TOTAL+255)/256, 256>>>(segs, (long)WALL_TOTAL);

        // ----- GAT -----
        gemm(hgat, 0, 896, 896, nullptr, hXP, NROWS_GAT, FIN, FIN, nullptr, 0);
        psd_kernel<<<NROWS_GAT,256>>>(hXP, a1_s, a1_d);
        alpha_kernel<<<BATCH,64>>>(nullptr, al1);
        gat_agg_kernel<<<BATCH,256>>>(al1, hXP, hgat, nullptr);
        gemm(hgat, 1, 896, 896, nullptr, hXP, NROWS_GAT, FIN, FIN, nullptr, 0);
        psd_kernel<<<NROWS_GAT,256>>>(hXP, a2_s, a2_d);
        alpha_kernel<<<BATCH,64>>>(al1, al2);
        gat_agg_kernel<<<BATCH,256>>>(al2, hXP, nullptr, bufA);
        sq_kernel<<<BATCH,256>>>(al2);
        dist_kernel<<<dim3(8,8),256>>>(al2, part);
        fin_dist_kernel<<<1,32>>>(out, out_size);
    }

    // ----- transformer -----
    {
        size_t no = (size_t)NROWS_TR*DT;
        build_out_kernel<<<(unsigned)((no+255)/256), 256>>>(times);
        for (int l=0; l<2; l++) {
            gemm(hx, 2+l, 192, 512, nullptr, qkvh, NROWS_TR, 3*DT, 3*DT,
                 attn_in_b + l*3*DT, 0);
            attn_kernel<<<dim3(BATCH,NHEAD),256,ATTN_SMEM>>>(qkvh, lengths, hatt);
            hgemm_ln_kernel<<<NROWS_TR/128,320,FSMEM>>>(hatt, hWall + WOFF[4+l],
                 x, hx, 192, attn_out_b + l*DT, ln1_g + l*DT, ln1_b + l*DT);
            gemm(hx, 6+l, 192, 128, nullptr, hff, NROWS_TR, NHID, NHID,
                 ff1_b + l*NHID, 1);
            hgemm_ln_kernel<<<NROWS_TR/128,320,FSMEM>>>(hff, hWall + WOFF[8+l],
                 x, hx, 128, ff2_b + l*DT, ln2_g + l*DT, ln2_b + l*DT);
        }
    }

    // ----- head -----
    agg_emb_kernel<<<BATCH,DFINAL>>>(lengths, statics, emb_w, emb_b);
    mlp_kernel<<<BATCH,DFINAL>>>(mlp1_w, mlp1_b, mlp2_w, mlp2_b, out);
}

// round 17
// speedup vs baseline: 1.1030x; 1.1030x over previous
#include <cuda_runtime.h>
#include <cuda_fp16.h>
#include <cstdint>
#include <math.h>
#include <mma.h>
using namespace nvcuda;

// ---------------- model constants ----------------
#define BATCH   512
#define S_LEN   215
#define DINP    36
#define DMODEL  144
#define DT      160
#define NHEAD   4
#define DH      40
#define NHID    128
#define FIN     860
#define FINP    896
#define DTP     192
#define DFINAL  196
#define NROWS_GAT (BATCH*DINP)          // 18432
#define NROWS_TR  (S_LEN*BATCH)         // 110080

// ---------------- scratch (device globals; zero-initialized at load) ----------------
__device__ float  g_bufA[(size_t)NROWS_GAT*FIN];    // H2 fp32 (feeds build_out)
__device__ float  g_ps[NROWS_GAT];
__device__ float  g_pd[NROWS_GAT];
__device__ float  g_alpha1[(size_t)BATCH*DINP*DINP];
__device__ float  g_alpha2[(size_t)BATCH*DINP*DINP];
__device__ float  g_sq[BATCH];
__device__ float  g_part[BATCH];
__device__ float  g_x[(size_t)NROWS_TR*DT];         // fp32 residual highway
__device__ float  g_feat[BATCH*DFINAL];
// fp16 operands; pad columns never written -> stay zero (module zero-init)
__device__ __half g_hgat[(size_t)NROWS_GAT*FINP];
__device__ __half g_hXP[(size_t)NROWS_GAT*FIN];
__device__ __half g_hx[(size_t)NROWS_TR*DTP];
__device__ __half g_hatt[(size_t)NROWS_TR*DTP];
__device__ __half g_hff[(size_t)NROWS_TR*NHID];
__device__ __half g_qkvh[(size_t)NROWS_TR*3*DT];
#define WALL_TOTAL 2015232
__device__ __half g_hWall[WALL_TOTAL];

// ---------------- utility ----------------
__global__ void zero_kernel(float* p, int n) {
    int i = blockIdx.x*blockDim.x + threadIdx.x;
    if (i < n) p[i] = 0.f;
}

__device__ __forceinline__ void cp16(uint32_t dst, const void* src) {
    asm volatile("cp.async.cg.shared.global [%0], [%1], 16;\n" :: "r"(dst), "l"(src));
}
__device__ __forceinline__ void cp_commit() {
    asm volatile("cp.async.commit_group;\n" ::: "memory");
}
__device__ __forceinline__ void cp_wait_all() {
    asm volatile("cp.async.wait_group 0;\n" ::: "memory");
}

// ---------------- all-weights transpose+convert (one launch) ----------------
struct WSeg { const float* src; int K, N, Kp, Npad; long off; };
struct WSegs { WSeg s[10]; };

__global__ void convW_kernel(WSegs segs, long total)
{
    long g = (long)blockIdx.x*blockDim.x + threadIdx.x;
    if (g >= total) return;
    int si = 0;
    #pragma unroll
    for (int i = 1; i < 10; i++) if (g >= segs.s[i].off) si = i;
    const WSeg& sg = segs.s[si];
    long i = g - sg.off;
    int k = (int)(i % sg.Kp), n = (int)(i / sg.Kp);
    float v = (k < sg.K && n < sg.N) ? sg.src[(size_t)k*sg.N + n] : 0.f;
    g_hWall[g] = __float2half(v);
}

// ---------------- FP16 tensor-core GEMM (256 thr, warp tile 64x32) ----------------
// Ch = act(Ah@Bt^T + bias), fp16 out (ld ldc; N and ldc even)
#define HKT 64
#define HLD 72
#define HSTG (128*HLD)
#define HSMEM (4*HSTG*2)
#define WLD 20

__global__ void __launch_bounds__(256, 2)
hgemm16_kernel(const __half* __restrict__ Ah, const __half* __restrict__ Bt,
               __half* __restrict__ Ch,
               int M, int N, int Kp, int ldc,
               const float* __restrict__ bias, int relu_flag)
{
    extern __shared__ __half hs[];
    __half* As0 = hs;
    __half* Bs0 = hs + HSTG;
    __half* As1 = hs + 2*HSTG;
    __half* Bs1 = hs + 3*HSTG;
    __shared__ float Wb[8][16*WLD];

    int tid = threadIdx.x;
    int warpId = tid >> 5, lane = tid & 31;
    int wr = warpId >> 2;
    int wc = warpId & 3;
    int row0 = blockIdx.y*128, col0 = blockIdx.x*128;

    wmma::fragment<wmma::accumulator,16,16,16,float> cf[4][2];
    #pragma unroll
    for (int i=0;i<4;i++)
      #pragma unroll
      for (int j=0;j<2;j++) wmma::fill_fragment(cf[i][j], 0.f);

    const int nIter = Kp / HKT;

    auto load_stage = [&](__half* as, __half* bs, int k0) {
        #pragma unroll
        for (int c = 0; c < 4; c++) {
            int ci = tid + c*256;
            int r = ci >> 3, c8 = (ci & 7)*8;
            cp16((uint32_t)__cvta_generic_to_shared(&as[r*HLD + c8]),
                 &Ah[(size_t)(row0 + r)*Kp + k0 + c8]);
        }
        #pragma unroll
        for (int c = 0; c < 4; c++) {
            int ci = tid + c*256;
            int r = ci >> 3, c8 = (ci & 7)*8;
            cp16((uint32_t)__cvta_generic_to_shared(&bs[r*HLD + c8]),
                 &Bt[(size_t)(col0 + r)*Kp + k0 + c8]);
        }
        cp_commit();
    };

    load_stage(As0, Bs0, 0);

    for (int it = 0; it < nIter; it++) {
        cp_wait_all();
        __syncthreads();
        __half* as = (it & 1) ? As1 : As0;
        __half* bs = (it & 1) ? Bs1 : Bs0;
        if (it + 1 < nIter)
            load_stage((it & 1) ? As0 : As1, (it & 1) ? Bs0 : Bs1, (it+1)*HKT);

        #pragma unroll
        for (int ks = 0; ks < HKT; ks += 16) {
            wmma::fragment<wmma::matrix_a,16,16,16,__half,wmma::row_major> af[4];
            wmma::fragment<wmma::matrix_b,16,16,16,__half,wmma::col_major> bf[2];
            #pragma unroll
            for (int fr=0; fr<4; fr++)
                wmma::load_matrix_sync(af[fr], &as[(wr*64 + fr*16)*HLD + ks], HLD);
            #pragma unroll
            for (int fc=0; fc<2; fc++)
                wmma::load_matrix_sync(bf[fc], &bs[(wc*32 + fc*16)*HLD + ks], HLD);
            #pragma unroll
            for (int fr=0; fr<4; fr++)
              #pragma unroll
              for (int fc=0; fc<2; fc++)
                wmma::mma_sync(cf[fr][fc], af[fr], bf[fc], cf[fr][fc]);
        }
        __syncthreads();
    }

    float* wbuf = Wb[warpId];
    #pragma unroll
    for (int fr=0; fr<4; fr++) {
        #pragma unroll
        for (int fc=0; fc<2; fc++) {
            wmma::store_matrix_sync(wbuf, cf[fr][fc], WLD, wmma::mem_row_major);
            __syncwarp();
            int rb = row0 + wr*64 + fr*16;
            int cb = col0 + wc*32 + fc*16;
            // 256 elems = 128 half2; each of 32 lanes writes 4 half2
            #pragma unroll
            for (int i = lane; i < 128; i += 32) {
                int r = i >> 3, c2 = (i & 7)*2;
                int gc = cb + c2;
                if (gc < N) {
                    float v0 = wbuf[r*WLD + c2];
                    float v1 = wbuf[r*WLD + c2 + 1];
                    if (bias) { v0 += bias[gc]; v1 += bias[gc+1]; }
                    if (relu_flag) { v0 = fmaxf(v0, 0.f); v1 = fmaxf(v1, 0.f); }
                    *(__half2*)&Ch[(size_t)(rb + r)*ldc + gc] = __floats2half2_rn(v0, v1);
                }
            }
            __syncwarp();
        }
    }
}

// ---------------- fused GEMM + residual + LayerNorm (N=160, 320 thr, 2x5 warps) ----------------
#define F_ASTG (128*HLD)
#define F_BSTG (160*HLD)
#define FSMEM_STAGE ((F_ASTG+F_BSTG)*2*2)   // 82944 B
#define FSMEM_EPI   (128*160*4)             // 81920 B
#define FSMEM (FSMEM_STAGE > FSMEM_EPI ? FSMEM_STAGE : FSMEM_EPI)

__global__ void __launch_bounds__(320, 2)
hgemm_ln_kernel(const __half* __restrict__ Ah, const __half* __restrict__ Bt,
                float* __restrict__ xio, __half* __restrict__ hxo,
                int Kp, const float* __restrict__ bias,
                const float* __restrict__ lg, const float* __restrict__ lb)
{
    extern __shared__ __half hs[];
    __half* As0 = hs;
    __half* Bs0 = hs + F_ASTG;
    __half* As1 = Bs0 + F_BSTG;
    __half* Bs1 = As1 + F_ASTG;
    float* Cs = (float*)hs;

    int tid = threadIdx.x;
    int w = tid >> 5, lane = tid & 31;
    int wr = w / 5, wc = w - wr*5;
    int row0 = blockIdx.x * 128;

    wmma::fragment<wmma::accumulator,16,16,16,float> cf[4][2];
    #pragma unroll
    for (int i=0;i<4;i++)
      #pragma unroll
      for (int j=0;j<2;j++) wmma::fill_fragment(cf[i][j], 0.f);

    const int nIter = Kp / HKT;

    auto load_stage = [&](__half* as, __half* bs, int k0) {
        #pragma unroll
        for (int c = 0; c < 4; c++) {
            int ci = tid + c*320;
            if (ci < 1024) {
                int r = ci >> 3, c8 = (ci & 7)*8;
                cp16((uint32_t)__cvta_generic_to_shared(&as[r*HLD + c8]),
                     &Ah[(size_t)(row0 + r)*Kp + k0 + c8]);
            }
        }
        #pragma unroll
        for (int c = 0; c < 4; c++) {
            int ci = tid + c*320;
            int r = ci >> 3, c8 = (ci & 7)*8;
            cp16((uint32_t)__cvta_generic_to_shared(&bs[r*HLD + c8]),
                 &Bt[(size_t)r*Kp + k0 + c8]);
        }
        cp_commit();
    };

    load_stage(As0, Bs0, 0);

    for (int it = 0; it < nIter; it++) {
        cp_wait_all();
        __syncthreads();
        __half* as = (it & 1) ? As1 : As0;
        __half* bs = (it & 1) ? Bs1 : Bs0;
        if (it + 1 < nIter)
            load_stage((it & 1) ? As0 : As1, (it & 1) ? Bs0 : Bs1, (it+1)*HKT);

        #pragma unroll
        for (int ks = 0; ks < HKT; ks += 16) {
            wmma::fragment<wmma::matrix_a,16,16,16,__half,wmma::row_major> af[4];
            wmma::fragment<wmma::matrix_b,16,16,16,__half,wmma::col_major> bf[2];
            #pragma unroll
            for (int fr=0; fr<4; fr++)
                wmma::load_matrix_sync(af[fr], &as[(wr*64 + fr*16)*HLD + ks], HLD);
            #pragma unroll
            for (int fc=0; fc<2; fc++)
                wmma::load_matrix_sync(bf[fc], &bs[(wc*32 + fc*16)*HLD + ks], HLD);
            #pragma unroll
            for (int fr=0; fr<4; fr++)
              #pragma unroll
              for (int fc=0; fc<2; fc++)
                wmma::mma_sync(cf[fr][fc], af[fr], bf[fc], cf[fr][fc]);
        }
        __syncthreads();
    }

    #pragma unroll
    for (int fr=0; fr<4; fr++)
      #pragma unroll
      for (int fc=0; fc<2; fc++)
        wmma::store_matrix_sync(&Cs[(wr*64 + fr*16)*160 + wc*32 + fc*16],
                                cf[fr][fc], 160, wmma::mem_row_major);
    __syncthreads();

    for (int r = w; r < 128; r += 10) {
        size_t grow = (size_t)(row0 + r);
        float v[5];
        float s = 0.f, q = 0.f;
        #pragma unroll
        for (int i=0;i<5;i++){
            int c = lane + 32*i;
            float val = Cs[r*160 + c] + bias[c] + xio[grow*DT + c];
            v[i]=val; s += val; q += val*val;
        }
        #pragma unroll
        for (int o=16;o>0;o>>=1){
            s += __shfl_xor_sync(0xffffffffu, s, o);
            q += __shfl_xor_sync(0xffffffffu, q, o);
        }
        float mean = s/(float)DT;
        float var  = q/(float)DT - mean*mean;
        float inv  = rsqrtf(var + 1e-5f);
        #pragma unroll
        for (int i=0;i<5;i++){
            int d = lane + 32*i;
            float rr = (v[i]-mean)*inv*lg[d] + lb[d];
            xio[grow*DT + d] = rr;
            hxo[grow*DTP + d] = __float2half(rr);
        }
    }
}

// ---------------- GAT ----------------
__global__ void build_x_kernel(const float* __restrict__ src, const float* __restrict__ R_u)
{
    size_t n = (size_t)blockIdx.x*blockDim.x + threadIdx.x;
    const size_t total = (size_t)NROWS_GAT*FIN;
    if (n >= total) return;
    int c = (int)(n % FIN);
    int row = (int)(n / FIN);
    int i = row % DINP, b = row / DINP;
    int s = c >> 2, o = c & 3;
    float v = src[((size_t)s*BATCH + b)*(2*DINP) + i];
    g_hgat[(size_t)row*FINP + c] = __float2half(fmaxf(v * R_u[i*4+o], 0.f));
}

#define FIN2 (FIN/2)
__global__ void psd_kernel(const __half* __restrict__ XP,
                           const float* __restrict__ a_s, const float* __restrict__ a_d)
{
    int row = blockIdx.x;
    const __half2* x2 = (const __half2*)(XP + (size_t)row*FIN);
    int t = threadIdx.x;
    float s1=0.f, s2=0.f;
    for (int c2=t; c2<FIN2; c2+=256) {
        float2 v = __half22float2(x2[c2]);
        s1 += v.x*a_s[2*c2] + v.y*a_s[2*c2+1];
        s2 += v.x*a_d[2*c2] + v.y*a_d[2*c2+1];
    }
    __shared__ float r1[256], r2[256];
    r1[t]=s1; r2[t]=s2; __syncthreads();
    for (int o=128;o>0;o>>=1){ if(t<o){r1[t]+=r1[t+o]; r2[t]+=r2[t+o];} __syncthreads(); }
    if (t==0){ g_ps[row]=r1[0]; g_pd[row]=r2[0]; }
}

__global__ void alpha_kernel(const float* __restrict__ edge, float* __restrict__ alpha)
{
    int b = blockIdx.x;
    int i = threadIdx.x;
    if (i >= DINP) return;
    const float* psb = g_ps + b*DINP;
    float pdi = g_pd[b*DINP+i];
    float e[DINP];
    float m = -1e30f;
    #pragma unroll
    for (int j=0;j<DINP;j++){
        float v = pdi + psb[j];
        v = (v > 0.f) ? v : 0.2f*v;
        e[j]=v; m = fmaxf(m,v);
    }
    float l=0.f;
    #pragma unroll
    for (int j=0;j<DINP;j++){ float w=expf(e[j]-m); e[j]=w; l+=w; }
    float inv = 1.f/l;
    size_t base = ((size_t)b*DINP + i)*DINP;
    #pragma unroll
    for (int j=0;j<DINP;j++){
        float a = e[j]*inv;
        if (edge) a *= edge[base+j];
        alpha[base+j] = a;
    }
}

__global__ void gat_agg_kernel(const float* __restrict__ alpha, const __half* __restrict__ XP,
                               __half* __restrict__ Hh, float* __restrict__ Hf)
{
    int b = blockIdx.x;
    __shared__ float al[DINP*DINP];
    for (int i=threadIdx.x;i<DINP*DINP;i+=blockDim.x) al[i]=alpha[(size_t)b*DINP*DINP+i];
    __syncthreads();
    const __half2* xp = (const __half2*)(XP + (size_t)b*DINP*FIN);
    for (int idx=threadIdx.x; idx<DINP*FIN2; idx+=blockDim.x){
        int i = idx/FIN2, c2 = idx%FIN2;
        float s0=0.f, s1=0.f;
        #pragma unroll 6
        for (int j=0;j<DINP;j++){
            float a = al[i*DINP+j];
            float2 v = __half22float2(xp[j*FIN2 + c2]);
            s0 += a*v.x; s1 += a*v.y;
        }
        size_t row = (size_t)b*DINP + i;
        if (Hh) *(__half2*)&Hh[row*FINP + 2*c2] = __floats2half2_rn(s0, s1);
        if (Hf) { Hf[row*FIN + 2*c2] = s0; Hf[row*FIN + 2*c2+1] = s1; }
    }
}

__global__ void sq_kernel(const float* __restrict__ A)
{
    int b = blockIdx.x; int t = threadIdx.x;
    float s=0.f;
    for (int i=t;i<DINP*DINP;i+=256){ float v=A[(size_t)b*DINP*DINP+i]; s+=v*v; }
    __shared__ float r[256];
    r[t]=s; __syncthreads();
    for (int o=128;o>0;o>>=1){ if(t<o) r[t]+=r[t+o]; __syncthreads(); }
    if (t==0) g_sq[b]=r[0];
}

// ---------------- tiled pairwise distance ----------------
#define DTILE 64
#define DCH 64
#define KD (DINP*DINP)
__global__ void dist_kernel(const float* __restrict__ A, float* __restrict__ partial)
{
    __shared__ float As[DTILE][DCH+5];
    __shared__ float Bs[DTILE][DCH+5];
    int i0 = blockIdx.y*DTILE, j0 = blockIdx.x*DTILE;
    int t = threadIdx.x;
    int tx = t & 15, ty = t >> 4;
    float dot[4][4];
    #pragma unroll
    for (int a=0;a<4;a++)
      #pragma unroll
      for (int b=0;b<4;b++) dot[a][b]=0.f;

    for (int c0 = 0; c0 < KD; c0 += DCH) {
        for (int l = t; l < DTILE*DCH; l += 256) {
            int r = l >> 6, c = l & 63;
            int gc = c0 + c;
            float va = 0.f, vb = 0.f;
            if (gc < KD) {
                va = A[(size_t)(i0+r)*KD + gc];
                vb = A[(size_t)(j0+r)*KD + gc];
            }
            As[r][c] = va;
            Bs[r][c] = vb;
        }
        __syncthreads();
        #pragma unroll 8
        for (int c = 0; c < DCH; c++) {
            float a[4], b[4];
            #pragma unroll
            for (int ii=0;ii<4;ii++) a[ii] = As[ty*4+ii][c];
            #pragma unroll
            for (int jj=0;jj<4;jj++) b[jj] = Bs[tx*4+jj][c];
            #pragma unroll
            for (int ii=0;ii<4;ii++)
              #pragma unroll
              for (int jj=0;jj<4;jj++) dot[ii][jj] += a[ii]*b[jj];
        }
        __syncthreads();
    }

    float loc = 0.f;
    #pragma unroll
    for (int ii=0;ii<4;ii++) {
        int i = i0 + ty*4 + ii;
        float sqi = g_sq[i];
        #pragma unroll
        for (int jj=0;jj<4;jj++) {
            int j = j0 + tx*4 + jj;
            float d2 = sqi + g_sq[j] - 2.f*dot[ii][jj];
            d2 = fmaxf(d2, 0.f);
            loc += sqrtf(d2 + 1e-12f);
        }
    }
    __shared__ float red[256];
    red[t] = loc; __syncthreads();
    for (int o=128;o>0;o>>=1){ if(t<o) red[t]+=red[t+o]; __syncthreads(); }
    if (t==0) partial[blockIdx.y*8 + blockIdx.x] = red[0];
}

__global__ void fin_dist_kernel(float* __restrict__ out, int out_size)
{
    if (threadIdx.x==0){
        float s=0.f;
        for (int i=0;i<64;i++) s += g_part[i];
        if (out_size > BATCH*2) out[BATCH*2] = s / ((float)BATCH*(float)BATCH);
    }
}

// ---------------- transformer input: fp32 x + fp16 mirror ----------------
__global__ void build_out_kernel(const float* __restrict__ times)
{
    size_t n = (size_t)blockIdx.x*blockDim.x + threadIdx.x;
    const size_t total = (size_t)NROWS_TR*DT;
    if (n >= total) return;
    int d = (int)(n % DT);
    size_t row = n / DT;
    int b = (int)(row % BATCH);
    int s = (int)(row / BATCH);
    float v;
    if (d < DMODEL) {
        v = g_bufA[((size_t)b*DINP + (d>>2))*FIN + s*4 + (d&3)];
    } else {
        int k = d - DMODEL;
        float tv = times[(size_t)s*BATCH + b];
        int kk = (k < 8) ? k : k-8;
        float ts = powf(215.0f, (float)kk/7.0f) * 100.0f;
        float sc = tv / ts;
        v = (k < 8) ? sinf(sc) : cosf(sc);
    }
    g_x[n] = v;
    g_hx[row*DTP + d] = __float2half(v);
}

// ---------------- tensor-core flash-style attention ----------------
#define AQ_ROWS 224
#define ALD 48
#define ATTN_SMEM (3*AQ_ROWS*ALD*2 + 8*256*4 + 8*256*2 + 8*16*48*4)
#define PSCALE 0.015625f

__global__ void __launch_bounds__(256)
attn_kernel(const __half* __restrict__ qkv, const int* __restrict__ lengths,
            __half* __restrict__ outh)
{
    extern __shared__ char smc[];
    __half* Qs = (__half*)smc;
    __half* Ks = Qs + AQ_ROWS*ALD;
    __half* Vs = Ks + AQ_ROWS*ALD;
    float*  Ss = (float*)(smc + 3*AQ_ROWS*ALD*2);
    __half* Ps = (__half*)(smc + 3*AQ_ROWS*ALD*2 + 8*256*4);
    float*  Os = (float*)(smc + 3*AQ_ROWS*ALD*2 + 8*256*4 + 8*256*2);

    int b = blockIdx.x, h = blockIdx.y;
    int tid = threadIdx.x;
    int w = tid >> 5, lane = tid & 31;
    int len = lengths[b];

    {
        uint32_t* z = (uint32_t*)smc;
        for (int i = tid; i < 3*AQ_ROWS*ALD/2; i += 256) z[i] = 0u;
    }
    __syncthreads();
    for (int idx = tid; idx < S_LEN*20; idx += 256) {
        int t = idx / 20, d2 = idx % 20;
        size_t base = ((size_t)t*BATCH + b)*(3*DT) + h*DH + 2*d2;
        __half2 qv = *(const __half2*)&qkv[base];
        __half2 kv = *(const __half2*)&qkv[base + DT];
        __half2 vv = *(const __half2*)&qkv[base + 2*DT];
        *(__half2*)&Qs[t*ALD + 2*d2] = qv;
        *(__half2*)&Ks[t*ALD + 2*d2] = kv;
        *(__half2*)&Vs[t*ALD + 2*d2] = vv;
    }
    for (int t = tid; t < AQ_ROWS; t += 256) Vs[t*ALD + 40] = __float2half(1.f);
    __syncthreads();

    const float scale = rsqrtf((float)DH);
    float* mySs = Ss + w*256;
    __half* myPs = Ps + w*256;
    float* myOs = Os + w*768;
    int nkt = (len + 15) >> 4;

    #pragma unroll
    for (int qi = 0; qi < 2; qi++) {
        int qt = w + qi*8;
        if (qt >= 14) continue;
        int rowbase = qt*16;

        wmma::fragment<wmma::accumulator,16,16,16,float> acc[3];
        #pragma unroll
        for (int n=0;n<3;n++) wmma::fill_fragment(acc[n], 0.f);

        for (int kt = 0; kt < nkt; kt++) {
            int kbase = kt*16;
            wmma::fragment<wmma::accumulator,16,16,16,float> sf;
            wmma::fill_fragment(sf, 0.f);
            #pragma unroll
            for (int kk = 0; kk < 3; kk++) {
                wmma::fragment<wmma::matrix_a,16,16,16,__half,wmma::row_major> qa;
                wmma::fragment<wmma::matrix_b,16,16,16,__half,wmma::col_major> kb;
                wmma::load_matrix_sync(qa, &Qs[rowbase*ALD + kk*16], ALD);
                wmma::load_matrix_sync(kb, &Ks[kbase*ALD + kk*16], ALD);
                wmma::mma_sync(sf, qa, kb, sf);
            }
            wmma::store_matrix_sync(mySs, sf, 16, wmma::mem_row_major);
            __syncwarp();
            #pragma unroll
            for (int e = lane; e < 256; e += 32) {
                int c = e & 15;
                int t = kbase + c;
                float wv = (t < len) ? __expf(mySs[e]*scale)*PSCALE : 0.f;
                myPs[e] = __float2half(wv);
            }
            __syncwarp();
            wmma::fragment<wmma::matrix_a,16,16,16,__half,wmma::row_major> pa;
            wmma::load_matrix_sync(pa, myPs, 16);
            #pragma unroll
            for (int n = 0; n < 3; n++) {
                wmma::fragment<wmma::matrix_b,16,16,16,__half,wmma::row_major> vb;
                wmma::load_matrix_sync(vb, &Vs[kbase*ALD + n*16], ALD);
                wmma::mma_sync(acc[n], pa, vb, acc[n]);
            }
        }

        #pragma unroll
        for (int n = 0; n < 3; n++)
            wmma::store_matrix_sync(&myOs[n*16], acc[n], ALD, wmma::mem_row_major);
        __syncwarp();

        #pragma unroll
        for (int e = lane; e < 16*20; e += 32) {
            int r = e / 20, d2 = e % 20;
            int s = rowbase + r;
            if (s >= S_LEN) continue;
            float inv = 1.f / myOs[r*ALD + 40];
            float o0 = myOs[r*ALD + 2*d2] * inv;
            float o1 = myOs[r*ALD + 2*d2+1] * inv;
            size_t ob = ((size_t)s*BATCH + b)*DTP + h*DH + 2*d2;
            *(__half2*)&outh[ob] = __floats2half2_rn(o0, o1);
        }
        __syncwarp();
    }
}

// ---------------- pooled features + static embedding ----------------
__global__ void agg_emb_kernel(const int* __restrict__ lengths,
                               const float* __restrict__ statics,
                               const float* __restrict__ emb_w, const float* __restrict__ emb_b)
{
    int b = blockIdx.x; int d = threadIdx.x;
    int len = lengths[b];
    if (d < DT) {
        float s = 0.f;
        for (int t=0;t<len;t++) s += g_x[((size_t)t*BATCH + b)*DT + d];
        g_feat[b*DFINAL+d] = s / ((float)len + 1.0f);
    } else if (d < DFINAL) {
        int j = d - DT;
        float s = emb_b[j];
        #pragma unroll
        for (int r=0;r<9;r++) s += statics[b*9+r]*emb_w[r*DINP+j];
        g_feat[b*DFINAL+d] = s;
    }
}

// ---------------- final MLP ----------------
__global__ void mlp_kernel(const float* __restrict__ w1, const float* __restrict__ b1,
                           const float* __restrict__ w2, const float* __restrict__ b2,
                           float* __restrict__ out)
{
    int b = blockIdx.x; int t = threadIdx.x;
    __shared__ float f[DFINAL], hd[DFINAL];
    f[t] = g_feat[b*DFINAL+t];
    __syncthreads();
    float s = b1[t];
    for (int r=0;r<DFINAL;r++) s += f[r]*w1[r*DFINAL+t];
    hd[t] = fmaxf(s, 0.f);
    __syncthreads();
    if (t < 2) {
        float s2 = b2[t];
        for (int r=0;r<DFINAL;r++) s2 += hd[r]*w2[r*2+t];
        out[b*2+t] = s2;
    }
}

// ---------------- launch ----------------
extern "C" void kernel_launch(void* const* d_in, const int* in_sizes, int n_in,
                              void* d_out, int out_size)
{
    const float* src    = (const float*)d_in[0];
    const float* statics= (const float*)d_in[1];
    const float* times  = (const float*)d_in[2];
    const int*   lengths= (const int*)d_in[3];
    const float* R_u    = (const float*)d_in[4];
    const float* emb_w  = (const float*)d_in[5];
    const float* emb_b  = (const float*)d_in[6];
    const float* W1     = (const float*)d_in[7];
    const float* a1_s   = (const float*)d_in[8];
    const float* a1_d   = (const float*)d_in[9];
    const float* W2     = (const float*)d_in[10];
    const float* a2_s   = (const float*)d_in[11];
    const float* a2_d   = (const float*)d_in[12];
    const float* attn_in_w  = (const float*)d_in[13];
    const float* attn_in_b  = (const float*)d_in[14];
    const float* attn_out_w = (const float*)d_in[15];
    const float* attn_out_b = (const float*)d_in[16];
    const float* ff1_w  = (const float*)d_in[17];
    const float* ff1_b  = (const float*)d_in[18];
    const float* ff2_w  = (const float*)d_in[19];
    const float* ff2_b  = (const float*)d_in[20];
    const float* ln1_g  = (const float*)d_in[21];
    const float* ln1_b  = (const float*)d_in[22];
    const float* ln2_g  = (const float*)d_in[23];
    const float* ln2_b  = (const float*)d_in[24];
    const float* mlp1_w = (const float*)d_in[25];
    const float* mlp1_b = (const float*)d_in[26];
    const float* mlp2_w = (const float*)d_in[27];
    const float* mlp2_b = (const float*)d_in[28];
    float* out = (float*)d_out;

    float *bufA, *al1, *al2, *x, *part;
    __half *hgat, *hXP, *hx, *hatt, *hff, *qkvh, *hWall;
    cudaGetSymbolAddress((void**)&bufA, g_bufA);
    cudaGetSymbolAddress((void**)&al1,  g_alpha1);
    cudaGetSymbolAddress((void**)&al2,  g_alpha2);
    cudaGetSymbolAddress((void**)&x,    g_x);
    cudaGetSymbolAddress((void**)&part, g_part);
    cudaGetSymbolAddress((void**)&hgat, g_hgat);
    cudaGetSymbolAddress((void**)&hXP,  g_hXP);
    cudaGetSymbolAddress((void**)&hx,   g_hx);
    cudaGetSymbolAddress((void**)&hatt, g_hatt);
    cudaGetSymbolAddress((void**)&hff,  g_hff);
    cudaGetSymbolAddress((void**)&qkvh, g_qkvh);
    cudaGetSymbolAddress((void**)&hWall,g_hWall);

    static bool attr_done = false;
    if (!attr_done) {
        cudaFuncSetAttribute(attn_kernel,
                             cudaFuncAttributeMaxDynamicSharedMemorySize, ATTN_SMEM);
        cudaFuncSetAttribute(hgemm16_kernel,
                             cudaFuncAttributeMaxDynamicSharedMemorySize, HSMEM);
        cudaFuncSetAttribute(hgemm_ln_kernel,
                             cudaFuncAttributeMaxDynamicSharedMemorySize, FSMEM);
        attr_done = true;
    }

    const long WOFF[10] = {0, 802816, 1605632, 1703936, 1802240, 1851392,
                           1900544, 1925120, 1949696, 1982464};
    WSegs segs;
    segs.s[0] = { W1, 860, 860, 896, 896, WOFF[0] };
    segs.s[1] = { W2, 860, 860, 896, 896, WOFF[1] };
    segs.s[2] = { attn_in_w,               160, 480, 192, 512, WOFF[2] };
    segs.s[3] = { attn_in_w + 160*480,     160, 480, 192, 512, WOFF[3] };
    segs.s[4] = { attn_out_w,              160, 160, 192, 256, WOFF[4] };
    segs.s[5] = { attn_out_w + 160*160,    160, 160, 192, 256, WOFF[5] };
    segs.s[6] = { ff1_w,                   160, 128, 192, 128, WOFF[6] };
    segs.s[7] = { ff1_w + 160*128,         160, 128, 192, 128, WOFF[7] };
    segs.s[8] = { ff2_w,                   128, 160, 128, 256, WOFF[8] };
    segs.s[9] = { ff2_w + 128*160,         128, 160, 128, 256, WOFF[9] };

    auto gemm = [&](const __half* Ah, int widx, int Kp, int Npad,
                    __half* Ch, int M, int N, int ldc,
                    const float* bias, int relu) {
        dim3 g(Npad/128, M/128);
        hgemm16_kernel<<<g,256,HSMEM>>>(Ah, hWall + WOFF[widx], Ch,
                                        M, N, Kp, ldc, bias, relu);
    };

    // launch order: zero(1) build_x(2) convW(3) hgemm(4) <- ncu window
    zero_kernel<<<(out_size+255)/256, 256>>>(out, out_size);

    {
        size_t nx = (size_t)NROWS_GAT*FIN;
        build_x_kernel<<<(unsigned)((nx+255)/256), 256>>>(src, R_u);
        convW_kernel<<<(WALL_TOTAL+255)/256, 256>>>(segs, (long)WALL_TOTAL);

        // ----- GAT -----
        gemm(hgat, 0, 896, 896, hXP, NROWS_GAT, FIN, FIN, nullptr, 0);
        psd_kernel<<<NROWS_GAT,256>>>(hXP, a1_s, a1_d);
        alpha_kernel<<<BATCH,64>>>(nullptr, al1);
        gat_agg_kernel<<<BATCH,256>>>(al1, hXP, hgat, nullptr);
        gemm(hgat, 1, 896, 896, hXP, NROWS_GAT, FIN, FIN, nullptr, 0);
        psd_kernel<<<NROWS_GAT,256>>>(hXP, a2_s, a2_d);
        alpha_kernel<<<BATCH,64>>>(al1, al2);
        gat_agg_kernel<<<BATCH,256>>>(al2, hXP, nullptr, bufA);
        sq_kernel<<<BATCH,256>>>(al2);
        dist_kernel<<<dim3(8,8),256>>>(al2, part);
        fin_dist_kernel<<<1,32>>>(out, out_size);
    }

    // ----- transformer -----
    {
        size_t no = (size_t)NROWS_TR*DT;
        build_out_kernel<<<(unsigned)((no+255)/256), 256>>>(times);
        for (int l=0; l<2; l++) {
            gemm(hx, 2+l, 192, 512, qkvh, NROWS_TR, 3*DT, 3*DT,
                 attn_in_b + l*3*DT, 0);
            attn_kernel<<<dim3(BATCH,NHEAD),256,ATTN_SMEM>>>(qkvh, lengths, hatt);
            hgemm_ln_kernel<<<NROWS_TR/128,320,FSMEM>>>(hatt, hWall + WOFF[4+l],
                 x, hx, 192, attn_out_b + l*DT, ln1_g + l*DT, ln1_b + l*DT);
            gemm(hx, 6+l, 192, 128, hff, NROWS_TR, NHID, NHID,
                 ff1_b + l*NHID, 1);
            hgemm_ln_kernel<<<NROWS_TR/128,320,FSMEM>>>(hff, hWall + WOFF[8+l],
                 x, hx, 128, ff2_b + l*DT, ln2_g + l*DT, ln2_b + l*DT);
        }
    }

    // ----- head -----
    agg_emb_kernel<<<BATCH,DFINAL>>>(lengths, statics, emb_w, emb_b);
    mlp_kernel<<<BATCH,DFINAL>>>(mlp1_w, mlp1_b, mlp2_w, mlp2_b, out);
}